// round 16
// baseline (speedup 1.0000x reference)
#include <cuda_runtime.h>

#define BD 4
#define TD 32
#define HD 224
#define WD 224
#define CD 3
#define NPIXELS (BD*TD*HD*WD)   // 6,422,528
#define N1 79
#define N2 9
#define NPAINT (N1 + N2)        // 88
#define NBOX (N1 + 2*N2)        // 97

#define ROWS_PER_BLK 8
#define NROWS (BD*TD*HD)        // 28,672
#define NBLK (NROWS / ROWS_PER_BLK)  // 3,584
#define TPB 224                 // 28 threads/row * 8 rows; each thread 8 contiguous px

// L2-only load (no L1 allocation): touch-once read stream
__device__ __forceinline__ void ldg256cg(const float* p, float* v) {
    asm volatile("ld.global.cg.v8.f32 {%0,%1,%2,%3,%4,%5,%6,%7}, [%8];"
                 : "=f"(v[0]), "=f"(v[1]), "=f"(v[2]), "=f"(v[3]),
                   "=f"(v[4]), "=f"(v[5]), "=f"(v[6]), "=f"(v[7])
                 : "l"(p));
}
// cache-streaming (evict-first) store: write stream stops competing with
// the read stream for L2 residency (R13 win)
__device__ __forceinline__ void stg256cs(float* p, const float* v) {
    asm volatile("st.global.cs.v8.f32 [%0], {%1,%2,%3,%4,%5,%6,%7,%8};"
                 :: "l"(p),
                    "f"(v[0]), "f"(v[1]), "f"(v[2]), "f"(v[3]),
                    "f"(v[4]), "f"(v[5]), "f"(v[6]), "f"(v[7])
                 : "memory");
}

__global__ void __launch_bounds__(TPB, 6) fused_kernel(
    const float* __restrict__ frames, const float* __restrict__ mask_token,
    const int* __restrict__ b, const int* __restrict__ t,
    const int* __restrict__ h, const int* __restrict__ w,
    const int* __restrict__ rb, const int* __restrict__ rt,
    const int* __restrict__ rh, const int* __restrict__ rw,
    float* __restrict__ out, float* __restrict__ M_out)
{
    // ---- tail block: visibility mask M[b,t] ----
    if (blockIdx.x == NBLK) {
        int bt = threadIdx.x;
        if (bt < BD * TD) {
            int bb = bt / TD, tt = bt % TD;
            float m = 0.0f;
            for (int i = 0; i < NBOX; i++) {
                int tlo = max(t[i] - 2, 0), thi = min(t[i] + 2, TD - 1);
                if (b[i] == bb && tt >= tlo && tt < thi) m = 1.0f;
            }
            M_out[bt] = m;
        }
        return;
    }

    __shared__ int s_n;
    __shared__ int s_hlo[NPAINT], s_hhi[NPAINT], s_wlo[NPAINT], s_whi[NPAINT];
    __shared__ unsigned char s_bit[NPAINT];

    int r0 = blockIdx.x * ROWS_PER_BLK;   // first global row; block never crosses (b,t)
    int h0 = r0 % HD;
    int bt = r0 / HD;
    int tt = bt % TD, bb = bt / TD;

    if (threadIdx.x == 0) s_n = 0;
    __syncthreads();

    // box culling against this block's (b, t, [h0, h0+8))
    if (threadIdx.x < NPAINT) {
        int i = threadIdx.x;
        int ti = __ldg(t + i);
        int tlo = max(ti - 2, 0), thi = min(ti + 2, TD - 1);
        if (__ldg(b + i) == bb && tt >= tlo && tt < thi) {
            int hi = __ldg(h + i);
            int hlo = max(hi - 25, 0), hhi = min(hi + 25, HD - 1);
            if (hlo < h0 + ROWS_PER_BLK && hhi > h0) {
                int slot = atomicAdd(&s_n, 1);
                int wi = __ldg(w + i);
                s_hlo[slot] = hlo;
                s_hhi[slot] = hhi;
                s_wlo[slot] = max(wi - 25, 0);
                s_whi[slot] = min(wi + 25, WD - 1);
                s_bit[slot] = (i < N1) ? 1 : 2;
            }
        }
    }
    __syncthreads();
    int ncov = s_n;

    // thread's 8 contiguous pixels: row = tid/28, w0 = (tid%28)*8
    size_t fbase = (size_t)blockIdx.x * (ROWS_PER_BLK * WD * CD) + threadIdx.x * 24;
    const float* src = frames + fbase;
    float* dst = out + fbase;

    float v[24];

    // flags first (cheap, smem-resident) so fully-covered segments skip loads
    unsigned int f = 0;                       // 2 bits per pixel, 8 px
    if (ncov > 0) {
        int hh = h0 + threadIdx.x / 28;
        int w0 = (threadIdx.x % 28) * 8;
        for (int s = 0; s < ncov; s++) {
            if (hh >= s_hlo[s] && hh < s_hhi[s]) {
                int wlo = s_wlo[s], whi = s_whi[s];
                unsigned int bit = s_bit[s];
                #pragma unroll
                for (int j = 0; j < 8; j++) {
                    int ww = w0 + j;
                    if (ww >= wlo && ww < whi) f |= bit << (j * 2);
                }
            }
        }
    }
    unsigned int covmask = (f | (f >> 1)) & 0x5555u;   // bit per pixel

    if (covmask != 0x5555u) {                 // at least one uncovered px: need src
        ldg256cg(src,      v);
        ldg256cg(src + 8,  v + 8);
        ldg256cg(src + 16, v + 16);
    }

    if (f != 0u) {
        float mt0 = __ldg(mask_token + 0), mt1 = __ldg(mask_token + 1), mt2 = __ldg(mask_token + 2);
        long long ridx = ((((long long)__ldg(rb) * TD + __ldg(rt)) * HD + __ldg(rh)) * WD + __ldg(rw)) * CD;
        float rt0 = __ldg(frames + ridx), rt1 = __ldg(frames + ridx + 1), rt2 = __ldg(frames + ridx + 2);

        #pragma unroll
        for (int j = 0; j < 8; j++) {
            unsigned int fj = (f >> (j * 2)) & 3u;
            if (fj) {
                bool r2 = (fj & 2u) != 0u;    // R2 wins over R1
                v[j*3+0] = r2 ? rt0 : mt0;
                v[j*3+1] = r2 ? rt1 : mt1;
                v[j*3+2] = r2 ? rt2 : mt2;
            }
        }
    }

    stg256cs(dst,      v);
    stg256cs(dst + 8,  v + 8);
    stg256cs(dst + 16, v + 16);
}

extern "C" void kernel_launch(void* const* d_in, const int* in_sizes, int n_in,
                              void* d_out, int out_size) {
    const float* frames     = (const float*)d_in[0];
    const float* mask_token = (const float*)d_in[1];
    const int* b  = (const int*)d_in[2];
    const int* t  = (const int*)d_in[3];
    const int* h  = (const int*)d_in[4];
    const int* w  = (const int*)d_in[5];
    const int* rb = (const int*)d_in[6];
    const int* rt = (const int*)d_in[7];
    const int* rh = (const int*)d_in[8];
    const int* rw = (const int*)d_in[9];

    float* out = (float*)d_out;
    float* M_out = out + (size_t)NPIXELS * CD;

    fused_kernel<<<NBLK + 1, TPB>>>(frames, mask_token, b, t, h, w,
                                    rb, rt, rh, rw, out, M_out);
}

// round 17
// speedup vs baseline: 1.0730x; 1.0730x over previous
#include <cuda_runtime.h>

#define BD 4
#define TD 32
#define HD 224
#define WD 224
#define CD 3
#define NPIXELS (BD*TD*HD*WD)   // 6,422,528
#define N1 79
#define N2 9
#define NPAINT (N1 + N2)        // 88
#define NBOX (N1 + 2*N2)        // 97

#define ROWS_PER_BLK 8
#define NROWS (BD*TD*HD)        // 28,672
#define NBLK (NROWS / ROWS_PER_BLK)  // 3,584
#define TPB 224                 // 28 threads/row * 8 rows; each thread 8 contiguous px

// read-only path + L2 evict-first: touch-once read stream (best measured)
__device__ __forceinline__ void ldg256ef(const float* p, float* v) {
    asm volatile("ld.global.nc.L2::evict_first.v8.f32 {%0,%1,%2,%3,%4,%5,%6,%7}, [%8];"
                 : "=f"(v[0]), "=f"(v[1]), "=f"(v[2]), "=f"(v[3]),
                   "=f"(v[4]), "=f"(v[5]), "=f"(v[6]), "=f"(v[7])
                 : "l"(p));
}
// cache-streaming (evict-first) store: write stream stops competing with
// the read stream for L2 residency (R13 win)
__device__ __forceinline__ void stg256cs(float* p, const float* v) {
    asm volatile("st.global.cs.v8.f32 [%0], {%1,%2,%3,%4,%5,%6,%7,%8};"
                 :: "l"(p),
                    "f"(v[0]), "f"(v[1]), "f"(v[2]), "f"(v[3]),
                    "f"(v[4]), "f"(v[5]), "f"(v[6]), "f"(v[7])
                 : "memory");
}

__global__ void __launch_bounds__(TPB, 6) fused_kernel(
    const float* __restrict__ frames, const float* __restrict__ mask_token,
    const int* __restrict__ b, const int* __restrict__ t,
    const int* __restrict__ h, const int* __restrict__ w,
    const int* __restrict__ rb, const int* __restrict__ rt,
    const int* __restrict__ rh, const int* __restrict__ rw,
    float* __restrict__ out, float* __restrict__ M_out)
{
    // ---- tail block: visibility mask M[b,t] ----
    if (blockIdx.x == NBLK) {
        int bt = threadIdx.x;
        if (bt < BD * TD) {
            int bb = bt / TD, tt = bt % TD;
            float m = 0.0f;
            for (int i = 0; i < NBOX; i++) {
                int tlo = max(t[i] - 2, 0), thi = min(t[i] + 2, TD - 1);
                if (b[i] == bb && tt >= tlo && tt < thi) m = 1.0f;
            }
            M_out[bt] = m;
        }
        return;
    }

    __shared__ int s_n;
    __shared__ int s_hlo[NPAINT], s_hhi[NPAINT], s_wlo[NPAINT], s_whi[NPAINT];
    __shared__ unsigned char s_bit[NPAINT];

    int r0 = blockIdx.x * ROWS_PER_BLK;   // first global row; block never crosses (b,t)
    int h0 = r0 % HD;
    int bt = r0 / HD;
    int tt = bt % TD, bb = bt / TD;

    if (threadIdx.x == 0) s_n = 0;
    __syncthreads();

    // box culling against this block's (b, t, [h0, h0+8))
    if (threadIdx.x < NPAINT) {
        int i = threadIdx.x;
        int ti = __ldg(t + i);
        int tlo = max(ti - 2, 0), thi = min(ti + 2, TD - 1);
        if (__ldg(b + i) == bb && tt >= tlo && tt < thi) {
            int hi = __ldg(h + i);
            int hlo = max(hi - 25, 0), hhi = min(hi + 25, HD - 1);
            if (hlo < h0 + ROWS_PER_BLK && hhi > h0) {
                int slot = atomicAdd(&s_n, 1);
                int wi = __ldg(w + i);
                s_hlo[slot] = hlo;
                s_hhi[slot] = hhi;
                s_wlo[slot] = max(wi - 25, 0);
                s_whi[slot] = min(wi + 25, WD - 1);
                s_bit[slot] = (i < N1) ? 1 : 2;
            }
        }
    }
    __syncthreads();
    int ncov = s_n;

    // thread's 8 contiguous pixels: row = tid/28, w0 = (tid%28)*8
    size_t fbase = (size_t)blockIdx.x * (ROWS_PER_BLK * WD * CD) + threadIdx.x * 24;
    const float* src = frames + fbase;
    float* dst = out + fbase;

    float v[24];

    // flags first (cheap, smem-resident) so fully-covered segments skip loads
    unsigned int f = 0;                       // 2 bits per pixel, 8 px
    if (ncov > 0) {
        int hh = h0 + threadIdx.x / 28;
        int w0 = (threadIdx.x % 28) * 8;
        for (int s = 0; s < ncov; s++) {
            if (hh >= s_hlo[s] && hh < s_hhi[s]) {
                int wlo = s_wlo[s], whi = s_whi[s];
                unsigned int bit = s_bit[s];
                #pragma unroll
                for (int j = 0; j < 8; j++) {
                    int ww = w0 + j;
                    if (ww >= wlo && ww < whi) f |= bit << (j * 2);
                }
            }
        }
    }
    unsigned int covmask = (f | (f >> 1)) & 0x5555u;   // bit per pixel

    if (covmask != 0x5555u) {                 // at least one uncovered px: need src
        ldg256ef(src,      v);
        ldg256ef(src + 8,  v + 8);
        ldg256ef(src + 16, v + 16);
    }

    if (f != 0u) {
        float mt0 = __ldg(mask_token + 0), mt1 = __ldg(mask_token + 1), mt2 = __ldg(mask_token + 2);
        long long ridx = ((((long long)__ldg(rb) * TD + __ldg(rt)) * HD + __ldg(rh)) * WD + __ldg(rw)) * CD;
        float rt0 = __ldg(frames + ridx), rt1 = __ldg(frames + ridx + 1), rt2 = __ldg(frames + ridx + 2);

        #pragma unroll
        for (int j = 0; j < 8; j++) {
            unsigned int fj = (f >> (j * 2)) & 3u;
            if (fj) {
                bool r2 = (fj & 2u) != 0u;    // R2 wins over R1
                v[j*3+0] = r2 ? rt0 : mt0;
                v[j*3+1] = r2 ? rt1 : mt1;
                v[j*3+2] = r2 ? rt2 : mt2;
            }
        }
    }

    stg256cs(dst,      v);
    stg256cs(dst + 8,  v + 8);
    stg256cs(dst + 16, v + 16);
}

extern "C" void kernel_launch(void* const* d_in, const int* in_sizes, int n_in,
                              void* d_out, int out_size) {
    const float* frames     = (const float*)d_in[0];
    const float* mask_token = (const float*)d_in[1];
    const int* b  = (const int*)d_in[2];
    const int* t  = (const int*)d_in[3];
    const int* h  = (const int*)d_in[4];
    const int* w  = (const int*)d_in[5];
    const int* rb = (const int*)d_in[6];
    const int* rt = (const int*)d_in[7];
    const int* rh = (const int*)d_in[8];
    const int* rw = (const int*)d_in[9];

    float* out = (float*)d_out;
    float* M_out = out + (size_t)NPIXELS * CD;

    fused_kernel<<<NBLK + 1, TPB>>>(frames, mask_token, b, t, h, w,
                                    rb, rt, rh, rw, out, M_out);
}